// round 10
// baseline (speedup 1.0000x reference)
#include <cuda_runtime.h>
#include <cstdint>

// ---------------- problem constants ----------------
#define B_   8
#define C_   64
#define O_   256
#define TE_  128
#define GT_  256
#define A_   32
#define TILES_PER_B 384   // 256 tiles (j0=0) + 128 tiles (j0=128, i>=128)
#define MT_  128          // pair-rows per CTA

// ---------------- device scratch (static; no allocations) ----------------
__device__ __align__(16) float g_uq  [B_ * O_ * GT_];            // u + q  (2 MB)
__device__ __align__(16) float g_v   [B_ * O_ * GT_];            // v      (2 MB)
__device__ __align__(16) float g_part[B_ * TILES_PER_B * GT_];   // per-tile partials (3 MB)

// ---------------- helpers ----------------
__device__ __forceinline__ uint32_t f2tf32(float f) {
    uint32_t r;
    asm("cvt.rna.tf32.f32 %0, %1;" : "=r"(r) : "f"(f));
    return r;
}

__device__ __forceinline__ void mma_tf32(float& d0, float& d1, float& d2, float& d3,
                                         uint32_t a0, uint32_t a1, uint32_t a2, uint32_t a3,
                                         uint32_t b0, uint32_t b1) {
    asm volatile(
        "mma.sync.aligned.m16n8k8.row.col.f32.tf32.tf32.f32 "
        "{%0,%1,%2,%3}, {%4,%5,%6,%7}, {%8,%9}, {%0,%1,%2,%3};"
        : "+f"(d0), "+f"(d1), "+f"(d2), "+f"(d3)
        : "r"(a0), "r"(a1), "r"(a2), "r"(a3), "r"(b0), "r"(b1));
}

// ---------------- smem layout (floats) for main kernel ----------------
#define PA 260                         // Abuf row stride (260 % 32 == 4 -> A frag loads conflict-free)
#define PW 264                         // Wbuf row stride (264 % 32 == 8 -> B frag loads conflict-free)
#define SM_ABUF 0                      // 128 x 260
#define SM_WBUF (MT_ * PA)             // 33280 : 32 x 264 weight chunk
#define SM_UQ   (SM_WBUF + 32 * PW)    // 41728 : 256
#define SM_BIAS (SM_UQ + 256)          // 41984 : 256
#define SM_COL  (SM_BIAS + 256)        // 42240 : 512
#define SM_FLOATS (SM_COL + 512)       // 42752 floats = 171008 bytes

// ============================================================================
// Kernel 0: u+q and v precompute.
//   uq[b,i,n] = sum_c xo[b,i,c] * W1[c,n] + sum_t code[b,t]*W1[132+t,n] + b1[n]
//   v [b,i,n] = sum_c xo[b,i,c] * W1[66+c,n]
// grid = 128 (8 batches x 16 groups of 16 objects), block = 256
// ============================================================================
__global__ void prep_kernel(const float* __restrict__ x, const float* __restrict__ code,
                            const float* __restrict__ w1, const float* __restrict__ b1) {
    __shared__ float xr[16][66];
    __shared__ float cbuf[TE_];
    const int b  = blockIdx.x >> 4;
    const int i0 = (blockIdx.x & 15) << 4;
    const int tid = threadIdx.x;

    for (int idx = tid; idx < 16 * 64; idx += 256) {
        int ch = idx >> 4, ii = idx & 15;
        xr[ii][ch] = x[(b * C_ + ch) * O_ + i0 + ii];
    }
    if (tid < 16) {
        int i = i0 + tid;
        xr[tid][64] = -1.0f + (2.0f / 15.0f) * (float)(i >> 4);   // yy
        xr[tid][65] = -1.0f + (2.0f / 15.0f) * (float)(i & 15);   // xx
    }
    if (tid < TE_) cbuf[tid] = code[b * TE_ + tid];
    __syncthreads();

    const int n = tid;   // 0..255 output feature
    float u[16], v[16];
#pragma unroll
    for (int ii = 0; ii < 16; ++ii) { u[ii] = 0.f; v[ii] = 0.f; }

    for (int c = 0; c < 66; ++c) {
        float wa = w1[c * GT_ + n];
        float wb = w1[(66 + c) * GT_ + n];
#pragma unroll
        for (int ii = 0; ii < 16; ++ii) {
            float xv = xr[ii][c];
            u[ii] += xv * wa;
            v[ii] += xv * wb;
        }
    }
    float cq = b1[n];
    for (int t = 0; t < TE_; ++t) cq += cbuf[t] * w1[(132 + t) * GT_ + n];

#pragma unroll
    for (int ii = 0; ii < 16; ++ii) {
        int row = b * O_ + i0 + ii;
        g_uq[row * GT_ + n] = u[ii] + cq;
        g_v [row * GT_ + n] = v[ii];
    }
}

// ============================================================================
// Fused 128x256x256 tf32 GEMM on smem Abuf, weights streamed from global.
// 512 threads = 16 warps in a 4(M) x 4(N) grid, warp tile 32x64, mma m16n8k8.
// Output (ReLU applied) written back into Abuf, as tf32 bits or fp32.
// ============================================================================
template<bool TF32OUT>
__device__ __forceinline__ void gemm256(float* smem, const float4* __restrict__ gw4, int tid) {
    uint32_t* As = (uint32_t*)(smem + SM_ABUF);
    uint32_t* Ws = (uint32_t*)(smem + SM_WBUF);
    const float* bias = smem + SM_BIAS;

    const int lane = tid & 31;
    const int wid  = tid >> 5;
    const int g = lane >> 2;      // group id 0..7
    const int t = lane & 3;       // thread-in-group 0..3
    const int m0 = (wid & 3) * 32;
    const int n0 = (wid >> 2) * 64;

    float acc[2][8][4];
#pragma unroll
    for (int mt = 0; mt < 2; ++mt)
#pragma unroll
        for (int nt = 0; nt < 8; ++nt) {
            float be = bias[n0 + nt * 8 + 2 * t];
            float bo = bias[n0 + nt * 8 + 2 * t + 1];
            acc[mt][nt][0] = be; acc[mt][nt][1] = bo;
            acc[mt][nt][2] = be; acc[mt][nt][3] = bo;
        }

    // A-fragment row bases (u32 offsets into Abuf)
    uint32_t rA[4];
    rA[0] = (uint32_t)(m0 + g)      * PA;
    rA[1] = (uint32_t)(m0 + g + 8)  * PA;
    rA[2] = (uint32_t)(m0 + g + 16) * PA;
    rA[3] = (uint32_t)(m0 + g + 24) * PA;

    // preload weight chunk 0 (32 rows x 256 cols)
    float4 pf[4];
#pragma unroll
    for (int p = 0; p < 4; ++p) pf[p] = gw4[tid + p * 512];
#pragma unroll
    for (int p = 0; p < 4; ++p) {
        int f = tid + p * 512;
        int k = f >> 6, n4 = f & 63;
        uint4 o;
        o.x = f2tf32(pf[p].x); o.y = f2tf32(pf[p].y);
        o.z = f2tf32(pf[p].z); o.w = f2tf32(pf[p].w);
        *(uint4*)(Ws + k * PW + n4 * 4) = o;
    }
    __syncthreads();

#pragma unroll 1
    for (int c = 0; c < 8; ++c) {
        if (c < 7) {   // prefetch next chunk into registers (overlaps MMA below)
#pragma unroll
            for (int p = 0; p < 4; ++p) pf[p] = gw4[(c + 1) * 2048 + tid + p * 512];
        }
#pragma unroll
        for (int s = 0; s < 4; ++s) {
            const int kb  = c * 32 + s * 8;   // absolute k for A
            const int klo = s * 8;            // chunk-local k for W
            uint32_t afr[2][4];
#pragma unroll
            for (int mt = 0; mt < 2; ++mt) {
                afr[mt][0] = As[rA[mt * 2 + 0] + kb + t];
                afr[mt][1] = As[rA[mt * 2 + 1] + kb + t];
                afr[mt][2] = As[rA[mt * 2 + 0] + kb + t + 4];
                afr[mt][3] = As[rA[mt * 2 + 1] + kb + t + 4];
            }
#pragma unroll
            for (int nt = 0; nt < 8; ++nt) {
                uint32_t b0 = Ws[(klo + t)     * PW + n0 + nt * 8 + g];
                uint32_t b1 = Ws[(klo + t + 4) * PW + n0 + nt * 8 + g];
                mma_tf32(acc[0][nt][0], acc[0][nt][1], acc[0][nt][2], acc[0][nt][3],
                         afr[0][0], afr[0][1], afr[0][2], afr[0][3], b0, b1);
                mma_tf32(acc[1][nt][0], acc[1][nt][1], acc[1][nt][2], acc[1][nt][3],
                         afr[1][0], afr[1][1], afr[1][2], afr[1][3], b0, b1);
            }
        }
        __syncthreads();                     // all reads of Wbuf (and, at c==7, Abuf) done
        if (c < 7) {
#pragma unroll
            for (int p = 0; p < 4; ++p) {
                int f = tid + p * 512;
                int k = f >> 6, n4 = f & 63;
                uint4 o;
                o.x = f2tf32(pf[p].x); o.y = f2tf32(pf[p].y);
                o.z = f2tf32(pf[p].z); o.w = f2tf32(pf[p].w);
                *(uint4*)(Ws + k * PW + n4 * 4) = o;
            }
            __syncthreads();
        }
    }

    // epilogue: ReLU, write back into Abuf (safe: Abuf fully consumed)
#pragma unroll
    for (int mt = 0; mt < 2; ++mt) {
        int r0 = m0 + mt * 16 + g;
#pragma unroll
        for (int nt = 0; nt < 8; ++nt) {
            int col = n0 + nt * 8 + 2 * t;
            float v0 = fmaxf(acc[mt][nt][0], 0.f);
            float v1 = fmaxf(acc[mt][nt][1], 0.f);
            float v2 = fmaxf(acc[mt][nt][2], 0.f);
            float v3 = fmaxf(acc[mt][nt][3], 0.f);
            if (TF32OUT) {
                uint32_t* d0 = As + (uint32_t)r0 * PA + col;
                d0[0] = f2tf32(v0); d0[1] = f2tf32(v1);
                uint32_t* d1 = As + (uint32_t)(r0 + 8) * PA + col;
                d1[0] = f2tf32(v2); d1[1] = f2tf32(v3);
            } else {
                float* d0 = (float*)As + (uint32_t)r0 * PA + col;
                d0[0] = v0; d0[1] = v1;
                float* d1 = (float*)As + (uint32_t)(r0 + 8) * PA + col;
                d1[0] = v2; d1[1] = v3;
            }
        }
    }
}

// ============================================================================
// Kernel 1: fused per-tile pipeline.
// Tile = (batch b, object i, 128 consecutive j). h1 built from uq + v,
// two tf32 GEMMs (g_theta layers 2,3), masked column sum -> g_part.
// grid = 8 * 384 = 3072, block = 512, dyn smem 171008 B.
// ============================================================================
__global__ void __launch_bounds__(512, 1)
main_kernel(const float* __restrict__ w2, const float* __restrict__ b2,
            const float* __restrict__ w3, const float* __restrict__ b3) {
    extern __shared__ float smem[];
    const int tid = threadIdx.x;
    const int cta = blockIdx.x;
    const int b = cta / TILES_PER_B;
    const int t = cta - b * TILES_PER_B;
    int i, j0;
    if (t < 256) { i = t;       j0 = 0;   }
    else         { i = t - 128; j0 = 128; }   // t in [256,384) -> i in [128,256)
    int count = i - j0 + 1;                    // qualifying rows (j <= i), >= 1 by construction
    if (count > MT_) count = MT_;

    if (tid < 256) smem[SM_UQ + tid] = g_uq[(b * O_ + i) * GT_ + tid];
    else           smem[SM_BIAS + tid - 256] = b2[tid - 256];
    __syncthreads();

    // ---- stage A: h1 = relu(uq + v[j]) -> tf32 in Abuf ----
    {
        const float4* v4  = (const float4*)(g_v + (size_t)(b * O_ + j0) * GT_);
        const float4* uq4 = (const float4*)(smem + SM_UQ);
#pragma unroll 4
        for (int idx = tid; idx < MT_ * 64; idx += 512) {
            int r = idx >> 6, n4 = idx & 63;
            float4 vv = v4[r * 64 + n4];
            float4 uu = uq4[n4];
            uint4 o;
            o.x = f2tf32(fmaxf(vv.x + uu.x, 0.f));
            o.y = f2tf32(fmaxf(vv.y + uu.y, 0.f));
            o.z = f2tf32(fmaxf(vv.z + uu.z, 0.f));
            o.w = f2tf32(fmaxf(vv.w + uu.w, 0.f));
            *(uint4*)(smem + SM_ABUF + r * PA + n4 * 4) = o;
        }
    }
    __syncthreads();

    // ---- g_theta layer 2: h2 = relu(h1 @ W2 + b2), tf32 back into Abuf ----
    gemm256<true>(smem, (const float4*)w2, tid);
    __syncthreads();

    if (tid < 256) smem[SM_BIAS + tid] = b3[tid];
    __syncthreads();

    // ---- g_theta layer 3: rel = relu(h2 @ W3 + b3), fp32 into Abuf ----
    gemm256<false>(smem, (const float4*)w3, tid);
    __syncthreads();

    // ---- masked column reduction over rows with j <= i ----
    {
        int half = tid >> 8;           // 0 or 1
        int n    = tid & 255;
        int rbeg = half * 64;
        int rend = min(count, rbeg + 64);
        float s = 0.f;
        for (int r = rbeg; r < rend; ++r) s += smem[SM_ABUF + r * PA + n];
        smem[SM_COL + tid] = s;
    }
    __syncthreads();
    if (tid < 256)
        g_part[(size_t)(b * TILES_PER_B + t) * GT_ + tid] =
            smem[SM_COL + tid] + smem[SM_COL + 256 + tid];
}

// ============================================================================
// Kernel 2: per-batch reduction of tile partials + f_phi MLP.
// grid = 8, block = 256.
// ============================================================================
__global__ void tail_kernel(const float* __restrict__ fw1, const float* __restrict__ fb1,
                            const float* __restrict__ fw2, const float* __restrict__ fb2,
                            const float* __restrict__ fw3, const float* __restrict__ fb3,
                            float* __restrict__ out) {
    __shared__ float s0[256];
    __shared__ float s1[256];
    const int b = blockIdx.x;
    const int n = threadIdx.x;

    float s = 0.f;
    const float* p = g_part + (size_t)b * TILES_PER_B * GT_ + n;
#pragma unroll 4
    for (int t = 0; t < TILES_PER_B; ++t) s += p[(size_t)t * GT_];
    s0[n] = s;
    __syncthreads();

    float a1 = fb1[n];
#pragma unroll 8
    for (int k = 0; k < 256; ++k) a1 += s0[k] * fw1[k * 256 + n];
    s1[n] = fmaxf(a1, 0.f);
    __syncthreads();

    float a2 = fb2[n];
#pragma unroll 8
    for (int k = 0; k < 256; ++k) a2 += s1[k] * fw2[k * 256 + n];
    s0[n] = fmaxf(a2, 0.f);
    __syncthreads();

    if (n < A_) {
        float a3 = fb3[n];
#pragma unroll 8
        for (int k = 0; k < 256; ++k) a3 += s0[k] * fw3[k * A_ + n];
        out[b * A_ + n] = a3;
    }
}

// ============================================================================
// Host launcher
// ============================================================================
extern "C" void kernel_launch(void* const* d_in, const int* in_sizes, int n_in,
                              void* d_out, int out_size) {
    const float* x    = (const float*)d_in[0];
    const float* code = (const float*)d_in[1];
    const float* gw1  = (const float*)d_in[2];
    const float* gb1  = (const float*)d_in[3];
    const float* gw2  = (const float*)d_in[4];
    const float* gb2  = (const float*)d_in[5];
    const float* gw3  = (const float*)d_in[6];
    const float* gb3  = (const float*)d_in[7];
    const float* fw1  = (const float*)d_in[8];
    const float* fb1  = (const float*)d_in[9];
    const float* fw2  = (const float*)d_in[10];
    const float* fb2  = (const float*)d_in[11];
    const float* fw3  = (const float*)d_in[12];
    const float* fb3  = (const float*)d_in[13];
    float* out = (float*)d_out;
    (void)in_sizes; (void)n_in; (void)out_size;

    cudaFuncSetAttribute(main_kernel, cudaFuncAttributeMaxDynamicSharedMemorySize,
                         SM_FLOATS * (int)sizeof(float));

    prep_kernel<<<128, 256>>>(x, code, gw1, gb1);
    main_kernel<<<B_ * TILES_PER_B, 512, SM_FLOATS * sizeof(float)>>>(gw2, gb2, gw3, gb3);
    tail_kernel<<<B_, 256>>>(fw1, fb1, fw2, fb2, fw3, fb3, out);
}

// round 11
// speedup vs baseline: 1.2661x; 1.2661x over previous
#include <cuda_runtime.h>
#include <cstdint>

// ---------------- problem constants ----------------
#define B_   8
#define C_   64
#define O_   256
#define TE_  128
#define GT_  256
#define A_   32
#define TILES_PER_B 257   // 32896 lower-tri pairs / 128 rows per tile (exact)
#define MT_  128          // packed pair-rows per CTA

// ---------------- device scratch (static; no allocations) ----------------
__device__ __align__(16) float g_uq  [B_ * O_ * GT_];            // u + q + b1 (2 MB)
__device__ __align__(16) float g_v   [B_ * O_ * GT_];            // v          (2 MB)
__device__ __align__(16) float g_part[B_ * TILES_PER_B * GT_];   // per-tile partials

// ---------------- helpers ----------------
__device__ __forceinline__ uint32_t f2tf32(float f) {
    uint32_t r;
    asm("cvt.rna.tf32.f32 %0, %1;" : "=r"(r) : "f"(f));
    return r;
}

__device__ __forceinline__ void mma_tf32(float& d0, float& d1, float& d2, float& d3,
                                         uint32_t a0, uint32_t a1, uint32_t a2, uint32_t a3,
                                         uint32_t b0, uint32_t b1) {
    asm volatile(
        "mma.sync.aligned.m16n8k8.row.col.f32.tf32.tf32.f32 "
        "{%0,%1,%2,%3}, {%4,%5,%6,%7}, {%8,%9}, {%0,%1,%2,%3};"
        : "+f"(d0), "+f"(d1), "+f"(d2), "+f"(d3)
        : "r"(a0), "r"(a1), "r"(a2), "r"(a3), "r"(b0), "r"(b1));
}

// triangular-number inversion: largest i with i(i+1)/2 <= p
__device__ __forceinline__ int tri_row(int p) {
    int i = (int)((sqrtf(8.0f * (float)p + 1.0f) - 1.0f) * 0.5f);
    while ((i + 1) * (i + 2) / 2 <= p) ++i;
    while (i * (i + 1) / 2 > p) --i;
    return i;
}

// ---------------- smem layout (floats) for main kernel ----------------
#define PA 260                          // Abuf row stride (260 % 32 == 4 -> conflict-free A frags)
#define PW 264                          // Wbuf row stride (264 % 32 == 8 -> conflict-free B frags)
#define SM_ABUF 0                       // 128 x 260 = 33280
#define SM_WBUF (MT_ * PA)              // 33280 : 2 x (32 x 264) double-buffered weight chunk
#define SM_BIAS (SM_WBUF + 2 * 32 * PW) // 50176 : 256
#define SM_COL  (SM_BIAS + 256)         // 50432 : 512
#define SM_FLOATS (SM_COL + 512)        // 50944 floats = 203776 bytes

// ============================================================================
// Kernel 0: u+q and v precompute (layer-1 factorization).
//   uq[b,i,n] = sum_c xo[b,i,c] W1[c,n] + sum_t code[b,t] W1[132+t,n] + b1[n]
//   v [b,i,n] = sum_c xo[b,i,c] W1[66+c,n]
// grid = 256 (8 batches x 32 groups of 8 objects), block = 256
// ============================================================================
__global__ void prep_kernel(const float* __restrict__ x, const float* __restrict__ code,
                            const float* __restrict__ w1, const float* __restrict__ b1) {
    __shared__ float xr[8][66];
    __shared__ float cbuf[TE_];
    const int b  = blockIdx.x >> 5;
    const int i0 = (blockIdx.x & 31) << 3;
    const int tid = threadIdx.x;

    for (int idx = tid; idx < 8 * 64; idx += 256) {
        int ch = idx >> 3, ii = idx & 7;
        xr[ii][ch] = x[(b * C_ + ch) * O_ + i0 + ii];
    }
    if (tid < 8) {
        int i = i0 + tid;
        xr[tid][64] = -1.0f + (2.0f / 15.0f) * (float)(i >> 4);   // yy
        xr[tid][65] = -1.0f + (2.0f / 15.0f) * (float)(i & 15);   // xx
    }
    if (tid < TE_) cbuf[tid] = code[b * TE_ + tid];
    __syncthreads();

    const int n = tid;   // 0..255 output feature
    float u[8], v[8];
#pragma unroll
    for (int ii = 0; ii < 8; ++ii) { u[ii] = 0.f; v[ii] = 0.f; }

#pragma unroll 2
    for (int c = 0; c < 66; ++c) {
        float wa = w1[c * GT_ + n];
        float wb = w1[(66 + c) * GT_ + n];
#pragma unroll
        for (int ii = 0; ii < 8; ++ii) {
            float xv = xr[ii][c];
            u[ii] += xv * wa;
            v[ii] += xv * wb;
        }
    }
    float cq = b1[n];
#pragma unroll 4
    for (int t = 0; t < TE_; ++t) cq += cbuf[t] * w1[(132 + t) * GT_ + n];

#pragma unroll
    for (int ii = 0; ii < 8; ++ii) {
        int row = b * O_ + i0 + ii;
        g_uq[row * GT_ + n] = u[ii] + cq;
        g_v [row * GT_ + n] = v[ii];
    }
}

// ============================================================================
// Fused 128x256x256 tf32 GEMM on smem Abuf, weights streamed (double-buffered)
// from global. 512 threads = 16 warps, 4(M) x 4(N) grid, warp tile 32x64,
// mma m16n8k8. A-fragments register-prefetched across the whole K loop.
// Output (ReLU applied) written back into Abuf, as tf32 bits or fp32.
// ============================================================================
template<bool TF32OUT>
__device__ __forceinline__ void gemm256(float* smem, const float4* __restrict__ gw4, int tid) {
    uint32_t* As = (uint32_t*)(smem + SM_ABUF);
    uint32_t* Ws = (uint32_t*)(smem + SM_WBUF);
    const float* bias = smem + SM_BIAS;

    const int lane = tid & 31;
    const int wid  = tid >> 5;
    const int g = lane >> 2;      // group id 0..7
    const int t = lane & 3;       // thread-in-group 0..3
    const int m0 = (wid & 3) * 32;
    const int n0 = (wid >> 2) * 64;

    float acc[2][8][4];
#pragma unroll
    for (int mt = 0; mt < 2; ++mt)
#pragma unroll
        for (int nt = 0; nt < 8; ++nt) {
            float be = bias[n0 + nt * 8 + 2 * t];
            float bo = bias[n0 + nt * 8 + 2 * t + 1];
            acc[mt][nt][0] = be; acc[mt][nt][1] = bo;
            acc[mt][nt][2] = be; acc[mt][nt][3] = bo;
        }

    // A-fragment row bases (u32 offsets into Abuf)
    uint32_t rA[4];
    rA[0] = (uint32_t)(m0 + g)      * PA;
    rA[1] = (uint32_t)(m0 + g + 8)  * PA;
    rA[2] = (uint32_t)(m0 + g + 16) * PA;
    rA[3] = (uint32_t)(m0 + g + 24) * PA;

    // global prefetch of weight chunk 0 (32 rows x 256 cols)
    float4 pf[4];
#pragma unroll
    for (int p = 0; p < 4; ++p) pf[p] = gw4[tid + p * 512];

    // A-fragment prefetch for k = 0 (Abuf stable for the whole GEMM)
    uint32_t afr[2][4];
#pragma unroll
    for (int mt = 0; mt < 2; ++mt) {
        afr[mt][0] = As[rA[mt * 2 + 0] + t];
        afr[mt][1] = As[rA[mt * 2 + 1] + t];
        afr[mt][2] = As[rA[mt * 2 + 0] + t + 4];
        afr[mt][3] = As[rA[mt * 2 + 1] + t + 4];
    }

#pragma unroll 1
    for (int c = 0; c < 8; ++c) {
        uint32_t* Wc = Ws + (c & 1) * 32 * PW;
        // store the prefetched chunk c (its buffer was last read at iter c-2,
        // separated by the barrier inside iter c-1)
#pragma unroll
        for (int p = 0; p < 4; ++p) {
            int f = tid + p * 512;
            int k = f >> 6, n4 = f & 63;
            uint4 o;
            o.x = f2tf32(pf[p].x); o.y = f2tf32(pf[p].y);
            o.z = f2tf32(pf[p].z); o.w = f2tf32(pf[p].w);
            *(uint4*)(Wc + k * PW + n4 * 4) = o;
        }
        if (c < 7) {   // issue global loads of chunk c+1 (consumed next iter)
#pragma unroll
            for (int p = 0; p < 4; ++p) pf[p] = gw4[(c + 1) * 2048 + tid + p * 512];
        }
        __syncthreads();

#pragma unroll
        for (int s = 0; s < 4; ++s) {
            const int klo = s * 8;            // chunk-local k for W
            // prefetch A-fragments for the next k-slice (pure Abuf, no barrier dep)
            uint32_t nafr[2][4];
            const int kn = c * 32 + klo + 8;
            if (kn < 256) {
#pragma unroll
                for (int mt = 0; mt < 2; ++mt) {
                    nafr[mt][0] = As[rA[mt * 2 + 0] + kn + t];
                    nafr[mt][1] = As[rA[mt * 2 + 1] + kn + t];
                    nafr[mt][2] = As[rA[mt * 2 + 0] + kn + t + 4];
                    nafr[mt][3] = As[rA[mt * 2 + 1] + kn + t + 4];
                }
            }
#pragma unroll
            for (int nt = 0; nt < 8; ++nt) {
                uint32_t b0 = Wc[(klo + t)     * PW + n0 + nt * 8 + g];
                uint32_t b1 = Wc[(klo + t + 4) * PW + n0 + nt * 8 + g];
                mma_tf32(acc[0][nt][0], acc[0][nt][1], acc[0][nt][2], acc[0][nt][3],
                         afr[0][0], afr[0][1], afr[0][2], afr[0][3], b0, b1);
                mma_tf32(acc[1][nt][0], acc[1][nt][1], acc[1][nt][2], acc[1][nt][3],
                         afr[1][0], afr[1][1], afr[1][2], afr[1][3], b0, b1);
            }
            if (kn < 256) {
#pragma unroll
                for (int mt = 0; mt < 2; ++mt)
#pragma unroll
                    for (int q = 0; q < 4; ++q) afr[mt][q] = nafr[mt][q];
            }
        }
    }

    __syncthreads();   // all Abuf reads done before epilogue overwrites it

    // epilogue: ReLU, write back into Abuf
#pragma unroll
    for (int mt = 0; mt < 2; ++mt) {
        int r0 = m0 + mt * 16 + g;
#pragma unroll
        for (int nt = 0; nt < 8; ++nt) {
            int col = n0 + nt * 8 + 2 * t;
            float v0 = fmaxf(acc[mt][nt][0], 0.f);
            float v1 = fmaxf(acc[mt][nt][1], 0.f);
            float v2 = fmaxf(acc[mt][nt][2], 0.f);
            float v3 = fmaxf(acc[mt][nt][3], 0.f);
            if (TF32OUT) {
                uint32_t* d0 = As + (uint32_t)r0 * PA + col;
                d0[0] = f2tf32(v0); d0[1] = f2tf32(v1);
                uint32_t* d1 = As + (uint32_t)(r0 + 8) * PA + col;
                d1[0] = f2tf32(v2); d1[1] = f2tf32(v3);
            } else {
                float* d0 = (float*)As + (uint32_t)r0 * PA + col;
                d0[0] = v0; d0[1] = v1;
                float* d1 = (float*)As + (uint32_t)(r0 + 8) * PA + col;
                d1[0] = v2; d1[1] = v3;
            }
        }
    }
}

// ============================================================================
// Kernel 1: fused per-tile pipeline over PACKED lower-triangular pairs.
// Tile t covers pair indices [t*128, t*128+128); pair p -> (i,j), j <= i.
// h1 rows built from uq[i] + v[j]; two tf32 GEMMs; full column sum -> g_part.
// grid = 8 * 257 = 2056, block = 512, dyn smem 203776 B.
// ============================================================================
__global__ void __launch_bounds__(512, 1)
main_kernel(const float* __restrict__ w2, const float* __restrict__ b2,
            const float* __restrict__ w3, const float* __restrict__ b3) {
    extern __shared__ float smem[];
    const int tid = threadIdx.x;
    const int b = blockIdx.x / TILES_PER_B;
    const int t = blockIdx.x - b * TILES_PER_B;
    const int p0 = t * MT_;

    if (tid < 256) smem[SM_BIAS + tid] = b2[tid];

    // ---- stage A: h1[r] = relu(uq[i_r] + v[j_r]) -> tf32 in Abuf ----
    {
        const float4* uq4 = (const float4*)(g_uq + (size_t)b * O_ * GT_);
        const float4* v4  = (const float4*)(g_v  + (size_t)b * O_ * GT_);
#pragma unroll 4
        for (int idx = tid; idx < MT_ * 64; idx += 512) {
            int r = idx >> 6, n4 = idx & 63;
            int p = p0 + r;
            int i = tri_row(p);
            int j = p - ((i * (i + 1)) >> 1);
            float4 uu = uq4[i * 64 + n4];
            float4 vv = v4 [j * 64 + n4];
            uint4 o;
            o.x = f2tf32(fmaxf(vv.x + uu.x, 0.f));
            o.y = f2tf32(fmaxf(vv.y + uu.y, 0.f));
            o.z = f2tf32(fmaxf(vv.z + uu.z, 0.f));
            o.w = f2tf32(fmaxf(vv.w + uu.w, 0.f));
            *(uint4*)(smem + SM_ABUF + r * PA + n4 * 4) = o;
        }
    }
    __syncthreads();

    // ---- g_theta layer 2: h2 = relu(h1 @ W2 + b2), tf32 back into Abuf ----
    gemm256<true>(smem, (const float4*)w2, tid);

    if (tid < 256) smem[SM_BIAS + tid] = b3[tid];
    __syncthreads();

    // ---- g_theta layer 3: rel = relu(h2 @ W3 + b3), fp32 into Abuf ----
    gemm256<false>(smem, (const float4*)w3, tid);
    __syncthreads();

    // ---- column reduction over all 128 packed rows ----
    {
        int half = tid >> 8;           // 0 or 1
        int n    = tid & 255;
        int rbeg = half * 64;
        float s = 0.f;
#pragma unroll 4
        for (int r = rbeg; r < rbeg + 64; ++r) s += smem[SM_ABUF + r * PA + n];
        smem[SM_COL + tid] = s;
    }
    __syncthreads();
    if (tid < 256)
        g_part[(size_t)(b * TILES_PER_B + t) * GT_ + tid] =
            smem[SM_COL + tid] + smem[SM_COL + 256 + tid];
}

// ============================================================================
// Kernel 2: per-batch reduction of tile partials + f_phi MLP.
// grid = 8, block = 256.
// ============================================================================
__global__ void tail_kernel(const float* __restrict__ fw1, const float* __restrict__ fb1,
                            const float* __restrict__ fw2, const float* __restrict__ fb2,
                            const float* __restrict__ fw3, const float* __restrict__ fb3,
                            float* __restrict__ out) {
    __shared__ float s0[256];
    __shared__ float s1[256];
    const int b = blockIdx.x;
    const int n = threadIdx.x;

    float s = 0.f;
    const float* p = g_part + (size_t)b * TILES_PER_B * GT_ + n;
#pragma unroll 4
    for (int t = 0; t < TILES_PER_B; ++t) s += p[(size_t)t * GT_];
    s0[n] = s;
    __syncthreads();

    float a1 = fb1[n];
#pragma unroll 8
    for (int k = 0; k < 256; ++k) a1 += s0[k] * fw1[k * 256 + n];
    s1[n] = fmaxf(a1, 0.f);
    __syncthreads();

    float a2 = fb2[n];
#pragma unroll 8
    for (int k = 0; k < 256; ++k) a2 += s1[k] * fw2[k * 256 + n];
    s0[n] = fmaxf(a2, 0.f);
    __syncthreads();

    if (n < A_) {
        float a3 = fb3[n];
#pragma unroll 8
        for (int k = 0; k < 256; ++k) a3 += s0[k] * fw3[k * A_ + n];
        out[b * A_ + n] = a3;
    }
}

// ============================================================================
// Host launcher
// ============================================================================
extern "C" void kernel_launch(void* const* d_in, const int* in_sizes, int n_in,
                              void* d_out, int out_size) {
    const float* x    = (const float*)d_in[0];
    const float* code = (const float*)d_in[1];
    const float* gw1  = (const float*)d_in[2];
    const float* gb1  = (const float*)d_in[3];
    const float* gw2  = (const float*)d_in[4];
    const float* gb2  = (const float*)d_in[5];
    const float* gw3  = (const float*)d_in[6];
    const float* gb3  = (const float*)d_in[7];
    const float* fw1  = (const float*)d_in[8];
    const float* fb1  = (const float*)d_in[9];
    const float* fw2  = (const float*)d_in[10];
    const float* fb2  = (const float*)d_in[11];
    const float* fw3  = (const float*)d_in[12];
    const float* fb3  = (const float*)d_in[13];
    float* out = (float*)d_out;
    (void)in_sizes; (void)n_in; (void)out_size;

    cudaFuncSetAttribute(main_kernel, cudaFuncAttributeMaxDynamicSharedMemorySize,
                         SM_FLOATS * (int)sizeof(float));

    prep_kernel<<<256, 256>>>(x, code, gw1, gb1);
    main_kernel<<<B_ * TILES_PER_B, 512, SM_FLOATS * sizeof(float)>>>(gw2, gb2, gw3, gb3);
    tail_kernel<<<B_, 256>>>(fw1, fb1, fw2, fb2, fw3, fb3, out);
}

// round 12
// speedup vs baseline: 1.2666x; 1.0004x over previous
#include <cuda_runtime.h>
#include <cstdint>

// ---------------- problem constants ----------------
#define B_   8
#define C_   64
#define O_   256
#define TE_  128
#define GT_  256
#define A_   32
#define TILES_PER_B 257   // 32896 lower-tri pairs / 128 rows per tile (exact)
#define MT_  128          // packed pair-rows per CTA

// ---------------- device scratch (static; no allocations) ----------------
__device__ __align__(16) float g_uq  [B_ * O_ * GT_];            // u + q + b1 (2 MB)
__device__ __align__(16) float g_v   [B_ * O_ * GT_];            // v          (2 MB)
__device__ __align__(16) float g_part[B_ * TILES_PER_B * GT_];   // per-tile partials

// ---------------- helpers ----------------
__device__ __forceinline__ uint32_t f2tf32(float f) {
    uint32_t r;
    asm("cvt.rna.tf32.f32 %0, %1;" : "=r"(r) : "f"(f));
    return r;
}

__device__ __forceinline__ void mma_tf32(float& d0, float& d1, float& d2, float& d3,
                                         uint32_t a0, uint32_t a1, uint32_t a2, uint32_t a3,
                                         uint32_t b0, uint32_t b1) {
    asm volatile(
        "mma.sync.aligned.m16n8k8.row.col.f32.tf32.tf32.f32 "
        "{%0,%1,%2,%3}, {%4,%5,%6,%7}, {%8,%9}, {%0,%1,%2,%3};"
        : "+f"(d0), "+f"(d1), "+f"(d2), "+f"(d3)
        : "r"(a0), "r"(a1), "r"(a2), "r"(a3), "r"(b0), "r"(b1));
}

// triangular-number inversion: largest i with i(i+1)/2 <= p
__device__ __forceinline__ int tri_row(int p) {
    int i = (int)((sqrtf(8.0f * (float)p + 1.0f) - 1.0f) * 0.5f);
    while ((i + 1) * (i + 2) / 2 <= p) ++i;
    while (i * (i + 1) / 2 > p) --i;
    return i;
}

// ---------------- smem layout (floats) for main kernel ----------------
#define PA 260                          // Abuf row stride (260 % 32 == 4 -> conflict-free A frags)
#define PW 264                          // Wbuf row stride (264 % 32 == 8 -> conflict-free B frags)
#define SM_ABUF 0                       // 128 x 260 = 33280
#define SM_WBUF (MT_ * PA)              // 33280 : 2 x (32 x 264) double-buffered weight chunk
#define SM_BIAS (SM_WBUF + 2 * 32 * PW) // 50176 : 256
#define SM_COL  (SM_BIAS + 256)         // 50432 : 512
#define SM_FLOATS (SM_COL + 512)        // 50944 floats = 203776 bytes

// ============================================================================
// Kernel 0: u+q and v precompute (layer-1 factorization).
//   uq[b,i,n] = sum_c xo[b,i,c] W1[c,n] + sum_t code[b,t] W1[132+t,n] + b1[n]
//   v [b,i,n] = sum_c xo[b,i,c] W1[66+c,n]
// grid = 256 (8 batches x 32 groups of 8 objects), block = 256
// ============================================================================
__global__ void prep_kernel(const float* __restrict__ x, const float* __restrict__ code,
                            const float* __restrict__ w1, const float* __restrict__ b1) {
    __shared__ float xr[8][66];
    __shared__ float cbuf[TE_];
    const int b  = blockIdx.x >> 5;
    const int i0 = (blockIdx.x & 31) << 3;
    const int tid = threadIdx.x;

    for (int idx = tid; idx < 8 * 64; idx += 256) {
        int ch = idx >> 3, ii = idx & 7;
        xr[ii][ch] = x[(b * C_ + ch) * O_ + i0 + ii];
    }
    if (tid < 8) {
        int i = i0 + tid;
        xr[tid][64] = -1.0f + (2.0f / 15.0f) * (float)(i >> 4);   // yy
        xr[tid][65] = -1.0f + (2.0f / 15.0f) * (float)(i & 15);   // xx
    }
    if (tid < TE_) cbuf[tid] = code[b * TE_ + tid];
    __syncthreads();

    const int n = tid;   // 0..255 output feature
    float u[8], v[8];
#pragma unroll
    for (int ii = 0; ii < 8; ++ii) { u[ii] = 0.f; v[ii] = 0.f; }

#pragma unroll 2
    for (int c = 0; c < 66; ++c) {
        float wa = w1[c * GT_ + n];
        float wb = w1[(66 + c) * GT_ + n];
#pragma unroll
        for (int ii = 0; ii < 8; ++ii) {
            float xv = xr[ii][c];
            u[ii] += xv * wa;
            v[ii] += xv * wb;
        }
    }
    float cq = b1[n];
#pragma unroll 4
    for (int t = 0; t < TE_; ++t) cq += cbuf[t] * w1[(132 + t) * GT_ + n];

#pragma unroll
    for (int ii = 0; ii < 8; ++ii) {
        int row = b * O_ + i0 + ii;
        g_uq[row * GT_ + n] = u[ii] + cq;
        g_v [row * GT_ + n] = v[ii];
    }
}

// ============================================================================
// Fused 128x256x256 tf32 GEMM on smem Abuf, weights streamed (double-buffered)
// from global. 512 threads = 16 warps, 4(M) x 4(N) grid, warp tile 32x64,
// mma m16n8k8. A-fragments register-prefetched across the whole K loop.
// Output (ReLU applied) written back into Abuf, as tf32 bits or fp32.
// ============================================================================
template<bool TF32OUT>
__device__ __forceinline__ void gemm256(float* smem, const float4* __restrict__ gw4, int tid) {
    uint32_t* As = (uint32_t*)(smem + SM_ABUF);
    uint32_t* Ws = (uint32_t*)(smem + SM_WBUF);
    const float* bias = smem + SM_BIAS;

    const int lane = tid & 31;
    const int wid  = tid >> 5;
    const int g = lane >> 2;      // group id 0..7
    const int t = lane & 3;       // thread-in-group 0..3
    const int m0 = (wid & 3) * 32;
    const int n0 = (wid >> 2) * 64;

    float acc[2][8][4];
#pragma unroll
    for (int mt = 0; mt < 2; ++mt)
#pragma unroll
        for (int nt = 0; nt < 8; ++nt) {
            float be = bias[n0 + nt * 8 + 2 * t];
            float bo = bias[n0 + nt * 8 + 2 * t + 1];
            acc[mt][nt][0] = be; acc[mt][nt][1] = bo;
            acc[mt][nt][2] = be; acc[mt][nt][3] = bo;
        }

    // A-fragment row bases (u32 offsets into Abuf)
    uint32_t rA[4];
    rA[0] = (uint32_t)(m0 + g)      * PA;
    rA[1] = (uint32_t)(m0 + g + 8)  * PA;
    rA[2] = (uint32_t)(m0 + g + 16) * PA;
    rA[3] = (uint32_t)(m0 + g + 24) * PA;

    // global prefetch of weight chunk 0 (32 rows x 256 cols)
    float4 pf[4];
#pragma unroll
    for (int p = 0; p < 4; ++p) pf[p] = gw4[tid + p * 512];

    // A-fragment prefetch for k = 0 (Abuf stable for the whole GEMM)
    uint32_t afr[2][4];
#pragma unroll
    for (int mt = 0; mt < 2; ++mt) {
        afr[mt][0] = As[rA[mt * 2 + 0] + t];
        afr[mt][1] = As[rA[mt * 2 + 1] + t];
        afr[mt][2] = As[rA[mt * 2 + 0] + t + 4];
        afr[mt][3] = As[rA[mt * 2 + 1] + t + 4];
    }

#pragma unroll 1
    for (int c = 0; c < 8; ++c) {
        uint32_t* Wc = Ws + (c & 1) * 32 * PW;
        // store the prefetched chunk c (its buffer was last read at iter c-2,
        // separated by the barrier inside iter c-1)
#pragma unroll
        for (int p = 0; p < 4; ++p) {
            int f = tid + p * 512;
            int k = f >> 6, n4 = f & 63;
            uint4 o;
            o.x = f2tf32(pf[p].x); o.y = f2tf32(pf[p].y);
            o.z = f2tf32(pf[p].z); o.w = f2tf32(pf[p].w);
            *(uint4*)(Wc + k * PW + n4 * 4) = o;
        }
        if (c < 7) {   // issue global loads of chunk c+1 (consumed next iter)
#pragma unroll
            for (int p = 0; p < 4; ++p) pf[p] = gw4[(c + 1) * 2048 + tid + p * 512];
        }
        __syncthreads();

#pragma unroll
        for (int s = 0; s < 4; ++s) {
            const int klo = s * 8;            // chunk-local k for W
            // prefetch A-fragments for the next k-slice (pure Abuf, no barrier dep)
            uint32_t nafr[2][4];
            const int kn = c * 32 + klo + 8;
            if (kn < 256) {
#pragma unroll
                for (int mt = 0; mt < 2; ++mt) {
                    nafr[mt][0] = As[rA[mt * 2 + 0] + kn + t];
                    nafr[mt][1] = As[rA[mt * 2 + 1] + kn + t];
                    nafr[mt][2] = As[rA[mt * 2 + 0] + kn + t + 4];
                    nafr[mt][3] = As[rA[mt * 2 + 1] + kn + t + 4];
                }
            }
#pragma unroll
            for (int nt = 0; nt < 8; ++nt) {
                uint32_t b0 = Wc[(klo + t)     * PW + n0 + nt * 8 + g];
                uint32_t b1 = Wc[(klo + t + 4) * PW + n0 + nt * 8 + g];
                mma_tf32(acc[0][nt][0], acc[0][nt][1], acc[0][nt][2], acc[0][nt][3],
                         afr[0][0], afr[0][1], afr[0][2], afr[0][3], b0, b1);
                mma_tf32(acc[1][nt][0], acc[1][nt][1], acc[1][nt][2], acc[1][nt][3],
                         afr[1][0], afr[1][1], afr[1][2], afr[1][3], b0, b1);
            }
            if (kn < 256) {
#pragma unroll
                for (int mt = 0; mt < 2; ++mt)
#pragma unroll
                    for (int q = 0; q < 4; ++q) afr[mt][q] = nafr[mt][q];
            }
        }
    }

    __syncthreads();   // all Abuf reads done before epilogue overwrites it

    // epilogue: ReLU, write back into Abuf
#pragma unroll
    for (int mt = 0; mt < 2; ++mt) {
        int r0 = m0 + mt * 16 + g;
#pragma unroll
        for (int nt = 0; nt < 8; ++nt) {
            int col = n0 + nt * 8 + 2 * t;
            float v0 = fmaxf(acc[mt][nt][0], 0.f);
            float v1 = fmaxf(acc[mt][nt][1], 0.f);
            float v2 = fmaxf(acc[mt][nt][2], 0.f);
            float v3 = fmaxf(acc[mt][nt][3], 0.f);
            if (TF32OUT) {
                uint32_t* d0 = As + (uint32_t)r0 * PA + col;
                d0[0] = f2tf32(v0); d0[1] = f2tf32(v1);
                uint32_t* d1 = As + (uint32_t)(r0 + 8) * PA + col;
                d1[0] = f2tf32(v2); d1[1] = f2tf32(v3);
            } else {
                float* d0 = (float*)As + (uint32_t)r0 * PA + col;
                d0[0] = v0; d0[1] = v1;
                float* d1 = (float*)As + (uint32_t)(r0 + 8) * PA + col;
                d1[0] = v2; d1[1] = v3;
            }
        }
    }
}

// ============================================================================
// Kernel 1: fused per-tile pipeline over PACKED lower-triangular pairs.
// Tile t covers pair indices [t*128, t*128+128); pair p -> (i,j), j <= i.
// h1 rows built from uq[i] + v[j]; two tf32 GEMMs; full column sum -> g_part.
// grid = 8 * 257 = 2056, block = 512, dyn smem 203776 B.
// ============================================================================
__global__ void __launch_bounds__(512, 1)
main_kernel(const float* __restrict__ w2, const float* __restrict__ b2,
            const float* __restrict__ w3, const float* __restrict__ b3) {
    extern __shared__ float smem[];
    const int tid = threadIdx.x;
    const int b = blockIdx.x / TILES_PER_B;
    const int t = blockIdx.x - b * TILES_PER_B;
    const int p0 = t * MT_;

    if (tid < 256) smem[SM_BIAS + tid] = b2[tid];

    // ---- stage A: h1[r] = relu(uq[i_r] + v[j_r]) -> tf32 in Abuf ----
    {
        const float4* uq4 = (const float4*)(g_uq + (size_t)b * O_ * GT_);
        const float4* v4  = (const float4*)(g_v  + (size_t)b * O_ * GT_);
#pragma unroll 4
        for (int idx = tid; idx < MT_ * 64; idx += 512) {
            int r = idx >> 6, n4 = idx & 63;
            int p = p0 + r;
            int i = tri_row(p);
            int j = p - ((i * (i + 1)) >> 1);
            float4 uu = uq4[i * 64 + n4];
            float4 vv = v4 [j * 64 + n4];
            uint4 o;
            o.x = f2tf32(fmaxf(vv.x + uu.x, 0.f));
            o.y = f2tf32(fmaxf(vv.y + uu.y, 0.f));
            o.z = f2tf32(fmaxf(vv.z + uu.z, 0.f));
            o.w = f2tf32(fmaxf(vv.w + uu.w, 0.f));
            *(uint4*)(smem + SM_ABUF + r * PA + n4 * 4) = o;
        }
    }
    __syncthreads();

    // ---- g_theta layer 2: h2 = relu(h1 @ W2 + b2), tf32 back into Abuf ----
    gemm256<true>(smem, (const float4*)w2, tid);

    if (tid < 256) smem[SM_BIAS + tid] = b3[tid];
    __syncthreads();

    // ---- g_theta layer 3: rel = relu(h2 @ W3 + b3), fp32 into Abuf ----
    gemm256<false>(smem, (const float4*)w3, tid);
    __syncthreads();

    // ---- column reduction over all 128 packed rows ----
    {
        int half = tid >> 8;           // 0 or 1
        int n    = tid & 255;
        int rbeg = half * 64;
        float s = 0.f;
#pragma unroll 4
        for (int r = rbeg; r < rbeg + 64; ++r) s += smem[SM_ABUF + r * PA + n];
        smem[SM_COL + tid] = s;
    }
    __syncthreads();
    if (tid < 256)
        g_part[(size_t)(b * TILES_PER_B + t) * GT_ + tid] =
            smem[SM_COL + tid] + smem[SM_COL + 256 + tid];
}

// ============================================================================
// Kernel 2: per-batch reduction of tile partials + f_phi MLP.
// grid = 8, block = 256.
// ============================================================================
__global__ void tail_kernel(const float* __restrict__ fw1, const float* __restrict__ fb1,
                            const float* __restrict__ fw2, const float* __restrict__ fb2,
                            const float* __restrict__ fw3, const float* __restrict__ fb3,
                            float* __restrict__ out) {
    __shared__ float s0[256];
    __shared__ float s1[256];
    const int b = blockIdx.x;
    const int n = threadIdx.x;

    float s = 0.f;
    const float* p = g_part + (size_t)b * TILES_PER_B * GT_ + n;
#pragma unroll 4
    for (int t = 0; t < TILES_PER_B; ++t) s += p[(size_t)t * GT_];
    s0[n] = s;
    __syncthreads();

    float a1 = fb1[n];
#pragma unroll 8
    for (int k = 0; k < 256; ++k) a1 += s0[k] * fw1[k * 256 + n];
    s1[n] = fmaxf(a1, 0.f);
    __syncthreads();

    float a2 = fb2[n];
#pragma unroll 8
    for (int k = 0; k < 256; ++k) a2 += s1[k] * fw2[k * 256 + n];
    s0[n] = fmaxf(a2, 0.f);
    __syncthreads();

    if (n < A_) {
        float a3 = fb3[n];
#pragma unroll 8
        for (int k = 0; k < 256; ++k) a3 += s0[k] * fw3[k * A_ + n];
        out[b * A_ + n] = a3;
    }
}

// ============================================================================
// Host launcher
// ============================================================================
extern "C" void kernel_launch(void* const* d_in, const int* in_sizes, int n_in,
                              void* d_out, int out_size) {
    const float* x    = (const float*)d_in[0];
    const float* code = (const float*)d_in[1];
    const float* gw1  = (const float*)d_in[2];
    const float* gb1  = (const float*)d_in[3];
    const float* gw2  = (const float*)d_in[4];
    const float* gb2  = (const float*)d_in[5];
    const float* gw3  = (const float*)d_in[6];
    const float* gb3  = (const float*)d_in[7];
    const float* fw1  = (const float*)d_in[8];
    const float* fb1  = (const float*)d_in[9];
    const float* fw2  = (const float*)d_in[10];
    const float* fb2  = (const float*)d_in[11];
    const float* fw3  = (const float*)d_in[12];
    const float* fb3  = (const float*)d_in[13];
    float* out = (float*)d_out;
    (void)in_sizes; (void)n_in; (void)out_size;

    cudaFuncSetAttribute(main_kernel, cudaFuncAttributeMaxDynamicSharedMemorySize,
                         SM_FLOATS * (int)sizeof(float));

    prep_kernel<<<256, 256>>>(x, code, gw1, gb1);
    main_kernel<<<B_ * TILES_PER_B, 512, SM_FLOATS * sizeof(float)>>>(gw2, gb2, gw3, gb3);
    tail_kernel<<<B_, 256>>>(fw1, fb1, fw2, fb2, fw3, fb3, out);
}

// round 13
// speedup vs baseline: 1.2701x; 1.0028x over previous
#include <cuda_runtime.h>
#include <cstdint>

// ---------------- problem constants ----------------
#define B_   8
#define C_   64
#define O_   256
#define TE_  128
#define GT_  256
#define A_   32
#define TILES_PER_B 257   // 32896 lower-tri pairs / 128 rows per tile (exact)
#define MT_  128          // packed pair-rows per CTA

// ---------------- device scratch (static; no allocations) ----------------
__device__ __align__(16) float g_uq  [B_ * O_ * GT_];            // u + q + b1 (2 MB)
__device__ __align__(16) float g_v   [B_ * O_ * GT_];            // v          (2 MB)
__device__ __align__(16) float g_part[B_ * TILES_PER_B * GT_];   // per-tile partials

// ---------------- helpers ----------------
__device__ __forceinline__ uint32_t f2tf32(float f) {
    uint32_t r;
    asm("cvt.rna.tf32.f32 %0, %1;" : "=r"(r) : "f"(f));
    return r;
}

__device__ __forceinline__ void mma_tf32(float& d0, float& d1, float& d2, float& d3,
                                         uint32_t a0, uint32_t a1, uint32_t a2, uint32_t a3,
                                         uint32_t b0, uint32_t b1) {
    asm volatile(
        "mma.sync.aligned.m16n8k8.row.col.f32.tf32.tf32.f32 "
        "{%0,%1,%2,%3}, {%4,%5,%6,%7}, {%8,%9}, {%0,%1,%2,%3};"
        : "+f"(d0), "+f"(d1), "+f"(d2), "+f"(d3)
        : "r"(a0), "r"(a1), "r"(a2), "r"(a3), "r"(b0), "r"(b1));
}

// triangular-number inversion: largest i with i(i+1)/2 <= p
__device__ __forceinline__ int tri_row(int p) {
    int i = (int)((sqrtf(8.0f * (float)p + 1.0f) - 1.0f) * 0.5f);
    while ((i + 1) * (i + 2) / 2 <= p) ++i;
    while (i * (i + 1) / 2 > p) --i;
    return i;
}

// ---------------- smem layout (floats) for main kernel ----------------
#define PA 260                          // Abuf row stride (260 % 32 == 4 -> conflict-free A frags)
#define PW 264                          // Wbuf row stride (264 % 32 == 8 -> conflict-free B frags)
#define SM_ABUF 0                       // 128 x 260 = 33280
#define SM_WBUF (MT_ * PA)              // 33280 : 2 x (32 x 264) double-buffered weight chunk
#define SM_BIAS (SM_WBUF + 2 * 32 * PW) // 50176 : 256
#define SM_COL  (SM_BIAS + 256)         // 50432 : 512
#define SM_FLOATS (SM_COL + 512)        // 50944 floats = 203776 bytes

// ============================================================================
// Kernel 0: u+q and v precompute (layer-1 factorization).
//   uq[b,i,n] = sum_c xo[b,i,c] W1[c,n] + sum_t code[b,t] W1[132+t,n] + b1[n]
//   v [b,i,n] = sum_c xo[b,i,c] W1[66+c,n]
// grid = 256 (8 batches x 32 groups of 8 objects), block = 256
// ============================================================================
__global__ void prep_kernel(const float* __restrict__ x, const float* __restrict__ code,
                            const float* __restrict__ w1, const float* __restrict__ b1) {
    __shared__ float xr[8][66];
    __shared__ float cbuf[TE_];
    const int b  = blockIdx.x >> 5;
    const int i0 = (blockIdx.x & 31) << 3;
    const int tid = threadIdx.x;

    for (int idx = tid; idx < 8 * 64; idx += 256) {
        int ch = idx >> 3, ii = idx & 7;
        xr[ii][ch] = x[(b * C_ + ch) * O_ + i0 + ii];
    }
    if (tid < 8) {
        int i = i0 + tid;
        xr[tid][64] = -1.0f + (2.0f / 15.0f) * (float)(i >> 4);   // yy
        xr[tid][65] = -1.0f + (2.0f / 15.0f) * (float)(i & 15);   // xx
    }
    if (tid < TE_) cbuf[tid] = code[b * TE_ + tid];
    __syncthreads();

    const int n = tid;   // 0..255 output feature
    float u[8], v[8];
#pragma unroll
    for (int ii = 0; ii < 8; ++ii) { u[ii] = 0.f; v[ii] = 0.f; }

#pragma unroll 2
    for (int c = 0; c < 66; ++c) {
        float wa = w1[c * GT_ + n];
        float wb = w1[(66 + c) * GT_ + n];
#pragma unroll
        for (int ii = 0; ii < 8; ++ii) {
            float xv = xr[ii][c];
            u[ii] += xv * wa;
            v[ii] += xv * wb;
        }
    }
    float cq = b1[n];
#pragma unroll 4
    for (int t = 0; t < TE_; ++t) cq += cbuf[t] * w1[(132 + t) * GT_ + n];

#pragma unroll
    for (int ii = 0; ii < 8; ++ii) {
        int row = b * O_ + i0 + ii;
        g_uq[row * GT_ + n] = u[ii] + cq;
        g_v [row * GT_ + n] = v[ii];
    }
}

// ============================================================================
// Fused 128x256x256 tf32 GEMM on smem Abuf, weights streamed (double-buffered)
// from global. 512 threads = 16 warps, 4(M) x 4(N) grid, warp tile 32x64,
// mma m16n8k8. A-fragments register-prefetched across the whole K loop.
// Output (ReLU applied) written back into Abuf, as tf32 bits or fp32.
// ============================================================================
template<bool TF32OUT>
__device__ __forceinline__ void gemm256(float* smem, const float4* __restrict__ gw4, int tid) {
    uint32_t* As = (uint32_t*)(smem + SM_ABUF);
    uint32_t* Ws = (uint32_t*)(smem + SM_WBUF);
    const float* bias = smem + SM_BIAS;

    const int lane = tid & 31;
    const int wid  = tid >> 5;
    const int g = lane >> 2;      // group id 0..7
    const int t = lane & 3;       // thread-in-group 0..3
    const int m0 = (wid & 3) * 32;
    const int n0 = (wid >> 2) * 64;

    float acc[2][8][4];
#pragma unroll
    for (int mt = 0; mt < 2; ++mt)
#pragma unroll
        for (int nt = 0; nt < 8; ++nt) {
            float be = bias[n0 + nt * 8 + 2 * t];
            float bo = bias[n0 + nt * 8 + 2 * t + 1];
            acc[mt][nt][0] = be; acc[mt][nt][1] = bo;
            acc[mt][nt][2] = be; acc[mt][nt][3] = bo;
        }

    // A-fragment row bases (u32 offsets into Abuf)
    uint32_t rA[4];
    rA[0] = (uint32_t)(m0 + g)      * PA;
    rA[1] = (uint32_t)(m0 + g + 8)  * PA;
    rA[2] = (uint32_t)(m0 + g + 16) * PA;
    rA[3] = (uint32_t)(m0 + g + 24) * PA;

    // global prefetch of weight chunk 0 (32 rows x 256 cols)
    float4 pf[4];
#pragma unroll
    for (int p = 0; p < 4; ++p) pf[p] = gw4[tid + p * 512];

    // A-fragment prefetch for k = 0 (Abuf stable for the whole GEMM)
    uint32_t afr[2][4];
#pragma unroll
    for (int mt = 0; mt < 2; ++mt) {
        afr[mt][0] = As[rA[mt * 2 + 0] + t];
        afr[mt][1] = As[rA[mt * 2 + 1] + t];
        afr[mt][2] = As[rA[mt * 2 + 0] + t + 4];
        afr[mt][3] = As[rA[mt * 2 + 1] + t + 4];
    }

#pragma unroll 1
    for (int c = 0; c < 8; ++c) {
        uint32_t* Wc = Ws + (c & 1) * 32 * PW;
        // store the prefetched chunk c (its buffer was last read at iter c-2,
        // separated by the barrier inside iter c-1)
#pragma unroll
        for (int p = 0; p < 4; ++p) {
            int f = tid + p * 512;
            int k = f >> 6, n4 = f & 63;
            uint4 o;
            o.x = f2tf32(pf[p].x); o.y = f2tf32(pf[p].y);
            o.z = f2tf32(pf[p].z); o.w = f2tf32(pf[p].w);
            *(uint4*)(Wc + k * PW + n4 * 4) = o;
        }
        if (c < 7) {   // issue global loads of chunk c+1 (consumed next iter)
#pragma unroll
            for (int p = 0; p < 4; ++p) pf[p] = gw4[(c + 1) * 2048 + tid + p * 512];
        }
        __syncthreads();

#pragma unroll
        for (int s = 0; s < 4; ++s) {
            const int klo = s * 8;            // chunk-local k for W
            // prefetch A-fragments for the next k-slice (pure Abuf, no barrier dep)
            uint32_t nafr[2][4];
            const int kn = c * 32 + klo + 8;
            if (kn < 256) {
#pragma unroll
                for (int mt = 0; mt < 2; ++mt) {
                    nafr[mt][0] = As[rA[mt * 2 + 0] + kn + t];
                    nafr[mt][1] = As[rA[mt * 2 + 1] + kn + t];
                    nafr[mt][2] = As[rA[mt * 2 + 0] + kn + t + 4];
                    nafr[mt][3] = As[rA[mt * 2 + 1] + kn + t + 4];
                }
            }
#pragma unroll
            for (int nt = 0; nt < 8; ++nt) {
                uint32_t b0 = Wc[(klo + t)     * PW + n0 + nt * 8 + g];
                uint32_t b1 = Wc[(klo + t + 4) * PW + n0 + nt * 8 + g];
                mma_tf32(acc[0][nt][0], acc[0][nt][1], acc[0][nt][2], acc[0][nt][3],
                         afr[0][0], afr[0][1], afr[0][2], afr[0][3], b0, b1);
                mma_tf32(acc[1][nt][0], acc[1][nt][1], acc[1][nt][2], acc[1][nt][3],
                         afr[1][0], afr[1][1], afr[1][2], afr[1][3], b0, b1);
            }
            if (kn < 256) {
#pragma unroll
                for (int mt = 0; mt < 2; ++mt)
#pragma unroll
                    for (int q = 0; q < 4; ++q) afr[mt][q] = nafr[mt][q];
            }
        }
    }

    __syncthreads();   // all Abuf reads done before epilogue overwrites it

    // epilogue: ReLU, write back into Abuf
#pragma unroll
    for (int mt = 0; mt < 2; ++mt) {
        int r0 = m0 + mt * 16 + g;
#pragma unroll
        for (int nt = 0; nt < 8; ++nt) {
            int col = n0 + nt * 8 + 2 * t;
            float v0 = fmaxf(acc[mt][nt][0], 0.f);
            float v1 = fmaxf(acc[mt][nt][1], 0.f);
            float v2 = fmaxf(acc[mt][nt][2], 0.f);
            float v3 = fmaxf(acc[mt][nt][3], 0.f);
            if (TF32OUT) {
                uint32_t* d0 = As + (uint32_t)r0 * PA + col;
                d0[0] = f2tf32(v0); d0[1] = f2tf32(v1);
                uint32_t* d1 = As + (uint32_t)(r0 + 8) * PA + col;
                d1[0] = f2tf32(v2); d1[1] = f2tf32(v3);
            } else {
                float* d0 = (float*)As + (uint32_t)r0 * PA + col;
                d0[0] = v0; d0[1] = v1;
                float* d1 = (float*)As + (uint32_t)(r0 + 8) * PA + col;
                d1[0] = v2; d1[1] = v3;
            }
        }
    }
}

// ============================================================================
// Kernel 1: fused per-tile pipeline over PACKED lower-triangular pairs.
// Tile t covers pair indices [t*128, t*128+128); pair p -> (i,j), j <= i.
// h1 rows built from uq[i] + v[j]; two tf32 GEMMs; full column sum -> g_part.
// grid = 8 * 257 = 2056, block = 512, dyn smem 203776 B.
// ============================================================================
__global__ void __launch_bounds__(512, 1)
main_kernel(const float* __restrict__ w2, const float* __restrict__ b2,
            const float* __restrict__ w3, const float* __restrict__ b3) {
    extern __shared__ float smem[];
    const int tid = threadIdx.x;
    const int b = blockIdx.x / TILES_PER_B;
    const int t = blockIdx.x - b * TILES_PER_B;
    const int p0 = t * MT_;

    if (tid < 256) smem[SM_BIAS + tid] = b2[tid];

    // ---- stage A: h1[r] = relu(uq[i_r] + v[j_r]) -> tf32 in Abuf ----
    {
        const float4* uq4 = (const float4*)(g_uq + (size_t)b * O_ * GT_);
        const float4* v4  = (const float4*)(g_v  + (size_t)b * O_ * GT_);
#pragma unroll 4
        for (int idx = tid; idx < MT_ * 64; idx += 512) {
            int r = idx >> 6, n4 = idx & 63;
            int p = p0 + r;
            int i = tri_row(p);
            int j = p - ((i * (i + 1)) >> 1);
            float4 uu = uq4[i * 64 + n4];
            float4 vv = v4 [j * 64 + n4];
            uint4 o;
            o.x = f2tf32(fmaxf(vv.x + uu.x, 0.f));
            o.y = f2tf32(fmaxf(vv.y + uu.y, 0.f));
            o.z = f2tf32(fmaxf(vv.z + uu.z, 0.f));
            o.w = f2tf32(fmaxf(vv.w + uu.w, 0.f));
            *(uint4*)(smem + SM_ABUF + r * PA + n4 * 4) = o;
        }
    }
    __syncthreads();

    // ---- g_theta layer 2: h2 = relu(h1 @ W2 + b2), tf32 back into Abuf ----
    gemm256<true>(smem, (const float4*)w2, tid);

    if (tid < 256) smem[SM_BIAS + tid] = b3[tid];
    __syncthreads();

    // ---- g_theta layer 3: rel = relu(h2 @ W3 + b3), fp32 into Abuf ----
    gemm256<false>(smem, (const float4*)w3, tid);
    __syncthreads();

    // ---- column reduction over all 128 packed rows ----
    {
        int half = tid >> 8;           // 0 or 1
        int n    = tid & 255;
        int rbeg = half * 64;
        float s = 0.f;
#pragma unroll 4
        for (int r = rbeg; r < rbeg + 64; ++r) s += smem[SM_ABUF + r * PA + n];
        smem[SM_COL + tid] = s;
    }
    __syncthreads();
    if (tid < 256)
        g_part[(size_t)(b * TILES_PER_B + t) * GT_ + tid] =
            smem[SM_COL + tid] + smem[SM_COL + 256 + tid];
}

// ============================================================================
// Kernel 2: per-batch reduction of tile partials + f_phi MLP.
// grid = 8, block = 256.
// ============================================================================
__global__ void tail_kernel(const float* __restrict__ fw1, const float* __restrict__ fb1,
                            const float* __restrict__ fw2, const float* __restrict__ fb2,
                            const float* __restrict__ fw3, const float* __restrict__ fb3,
                            float* __restrict__ out) {
    __shared__ float s0[256];
    __shared__ float s1[256];
    const int b = blockIdx.x;
    const int n = threadIdx.x;

    float s = 0.f;
    const float* p = g_part + (size_t)b * TILES_PER_B * GT_ + n;
#pragma unroll 4
    for (int t = 0; t < TILES_PER_B; ++t) s += p[(size_t)t * GT_];
    s0[n] = s;
    __syncthreads();

    float a1 = fb1[n];
#pragma unroll 8
    for (int k = 0; k < 256; ++k) a1 += s0[k] * fw1[k * 256 + n];
    s1[n] = fmaxf(a1, 0.f);
    __syncthreads();

    float a2 = fb2[n];
#pragma unroll 8
    for (int k = 0; k < 256; ++k) a2 += s1[k] * fw2[k * 256 + n];
    s0[n] = fmaxf(a2, 0.f);
    __syncthreads();

    if (n < A_) {
        float a3 = fb3[n];
#pragma unroll 8
        for (int k = 0; k < 256; ++k) a3 += s0[k] * fw3[k * A_ + n];
        out[b * A_ + n] = a3;
    }
}

// ============================================================================
// Host launcher
// ============================================================================
extern "C" void kernel_launch(void* const* d_in, const int* in_sizes, int n_in,
                              void* d_out, int out_size) {
    const float* x    = (const float*)d_in[0];
    const float* code = (const float*)d_in[1];
    const float* gw1  = (const float*)d_in[2];
    const float* gb1  = (const float*)d_in[3];
    const float* gw2  = (const float*)d_in[4];
    const float* gb2  = (const float*)d_in[5];
    const float* gw3  = (const float*)d_in[6];
    const float* gb3  = (const float*)d_in[7];
    const float* fw1  = (const float*)d_in[8];
    const float* fb1  = (const float*)d_in[9];
    const float* fw2  = (const float*)d_in[10];
    const float* fb2  = (const float*)d_in[11];
    const float* fw3  = (const float*)d_in[12];
    const float* fb3  = (const float*)d_in[13];
    float* out = (float*)d_out;
    (void)in_sizes; (void)n_in; (void)out_size;

    cudaFuncSetAttribute(main_kernel, cudaFuncAttributeMaxDynamicSharedMemorySize,
                         SM_FLOATS * (int)sizeof(float));

    prep_kernel<<<256, 256>>>(x, code, gw1, gb1);
    main_kernel<<<B_ * TILES_PER_B, 512, SM_FLOATS * sizeof(float)>>>(gw2, gb2, gw3, gb3);
    tail_kernel<<<B_, 256>>>(fw1, fb1, fw2, fb2, fw3, fb3, out);
}